// round 1
// baseline (speedup 1.0000x reference)
#include <cuda_runtime.h>

#define B_ 2048
#define K_ 8
#define O_ 256
#define I_ 512
#define TINY_ 1e-10f

// Scratch (allocation-free requirement): __device__ globals.
__device__ float g_sigma[K_ * O_ * I_];   // exp(log_sigma), 4 MB
__device__ int   g_idx[B_];               // selected component per batch

// --- Kernel 1: sigma = exp(log_sigma), computed ONCE (1M elems) ----------
__global__ void prep_sigma_kernel(const float* __restrict__ log_sigma) {
    int i = blockIdx.x * blockDim.x + threadIdx.x;
    if (i < K_ * O_ * I_) g_sigma[i] = expf(log_sigma[i]);
}

// --- Kernel 2: per-batch argmax of (mix_weights[k] + gumbel(u))/tau ------
// tau = 1.0; straight-through hard forward == pure one-hot of the argmax.
__global__ void prep_idx_kernel(const float* __restrict__ u_gumbel,
                                const float* __restrict__ mix_weights) {
    int b = blockIdx.x * blockDim.x + threadIdx.x;
    if (b >= B_) return;
    float best = -3.402823466e+38f;
    int best_k = 0;
#pragma unroll
    for (int k = 0; k < K_; k++) {
        float u = u_gumbel[b * K_ + k];
        float g = -logf(-logf(u + TINY_) + TINY_);
        float s = mix_weights[k] + g;   // / TAU (=1)
        if (s > best) { best = s; best_k = k; }   // first-index tie-break, matches jnp.argmax
    }
    g_idx[b] = best_k;
}

// --- Kernel 3: out[b,o] = sum_i X[b,i]*(mean[k,o,i] + sigma[k,o,i]*eps[b,o,i])
// One warp per output element. I=512 -> 128 float4 per array, 4 per lane,
// lane-interleaved so every load instruction is a fully-coalesced 512B.
__global__ void __launch_bounds__(256, 8)
bayes_linear_kernel(const float* __restrict__ X,
                    const float* __restrict__ mean,
                    const float* __restrict__ eps,
                    float* __restrict__ out) {
    const int warp = threadIdx.x >> 5;
    const int lane = threadIdx.x & 31;
    const int w = blockIdx.x * 8 + warp;       // w = b*O + o
    const int b = w >> 8;                      // / O_ (=256)
    const int o = w & (O_ - 1);
    const int k = g_idx[b];

    const float4* __restrict__ xp = (const float4*)(X + (size_t)b * I_);
    const float4* __restrict__ mp = (const float4*)(mean + ((size_t)k * O_ + o) * I_);
    const float4* __restrict__ sp = (const float4*)(g_sigma + ((size_t)k * O_ + o) * I_);
    const float4* __restrict__ ep = (const float4*)(eps + ((size_t)b * O_ + o) * I_);

    float acc = 0.0f;
#pragma unroll
    for (int j = 0; j < 4; j++) {
        const int v = j * 32 + lane;           // coalesced across the warp
        float4 x = __ldg(xp + v);              // reused across 256 o's -> cache
        float4 m = __ldg(mp + v);              // reused across ~B/K batches -> L2
        float4 s = __ldg(sp + v);
        float4 e = __ldcs(ep + v);             // streamed once: evict-first
        acc = fmaf(x.x, fmaf(s.x, e.x, m.x), acc);
        acc = fmaf(x.y, fmaf(s.y, e.y, m.y), acc);
        acc = fmaf(x.z, fmaf(s.z, e.z, m.z), acc);
        acc = fmaf(x.w, fmaf(s.w, e.w, m.w), acc);
    }

    // warp tree-reduce
#pragma unroll
    for (int off = 16; off; off >>= 1)
        acc += __shfl_xor_sync(0xFFFFFFFFu, acc, off);

    if (lane == 0) out[w] = acc;
}

extern "C" void kernel_launch(void* const* d_in, const int* in_sizes, int n_in,
                              void* d_out, int out_size) {
    const float* X         = (const float*)d_in[0];   // [B, I]
    const float* mixw      = (const float*)d_in[1];   // [K]
    const float* mean      = (const float*)d_in[2];   // [K, O, I]
    const float* log_sigma = (const float*)d_in[3];   // [K, O, I]
    const float* u_gumbel  = (const float*)d_in[4];   // [B, K]
    const float* eps       = (const float*)d_in[5];   // [B, O, I]
    float* out = (float*)d_out;                       // [B, O]

    prep_sigma_kernel<<<(K_ * O_ * I_ + 255) / 256, 256>>>(log_sigma);
    prep_idx_kernel<<<(B_ + 255) / 256, 256>>>(u_gumbel, mixw);
    bayes_linear_kernel<<<(B_ * O_) / 8, 256>>>(X, mean, eps, out);
}

// round 2
// speedup vs baseline: 1.0461x; 1.0461x over previous
#include <cuda_runtime.h>

#define B_ 2048
#define K_ 8
#define O_ 256
#define I_ 512
#define TINY_ 1e-10f

// Scratch (allocation-free requirement): __device__ globals.
__device__ float4 g_sigma4[K_ * O_ * I_ / 4];   // exp(log_sigma), 4 MB
__device__ int    g_idx[B_];                    // selected component per batch

// --- Kernel 1: sigma = exp(log_sigma), vectorized float4 + fast exp -------
__global__ void prep_sigma_kernel(const float4* __restrict__ log_sigma) {
    int i = blockIdx.x * blockDim.x + threadIdx.x;
    float4 v = log_sigma[i];
    float4 r;
    r.x = __expf(v.x); r.y = __expf(v.y); r.z = __expf(v.z); r.w = __expf(v.w);
    g_sigma4[i] = r;
}

// --- Kernel 2: per-batch argmax of mix_weights[k] + gumbel(u) (tau=1) -----
__global__ void prep_idx_kernel(const float* __restrict__ u_gumbel,
                                const float* __restrict__ mix_weights) {
    int b = blockIdx.x * blockDim.x + threadIdx.x;
    if (b >= B_) return;
    float best = -3.402823466e+38f;
    int best_k = 0;
#pragma unroll
    for (int k = 0; k < K_; k++) {
        float u = u_gumbel[b * K_ + k];
        float g = -logf(-logf(u + TINY_) + TINY_);
        float s = mix_weights[k] + g;
        if (s > best) { best = s; best_k = k; }   // first-index tie-break == jnp.argmax
    }
    g_idx[b] = best_k;
}

// --- Kernel 3: out[b,o] = sum_i X[b,i]*(mean[k,o,i] + sigma[k,o,i]*eps[b,o,i])
// Block = one b, 16 consecutive o. X row staged in smem once per block.
// Each warp owns 2 o's -> 24 independent float4 loads front-batched per warp.
__global__ void __launch_bounds__(256, 6)
bayes_linear_kernel(const float* __restrict__ X,
                    const float* __restrict__ mean,
                    const float* __restrict__ eps,
                    float* __restrict__ out) {
    __shared__ float4 xs[I_ / 4];     // 2 KB

    const int b  = blockIdx.x >> 4;          // O/16 = 16 blocks per batch
    const int o0 = (blockIdx.x & 15) * 16;
    const int warp = threadIdx.x >> 5;
    const int lane = threadIdx.x & 31;

    if (threadIdx.x < I_ / 4)
        xs[threadIdx.x] = ((const float4*)(X + (size_t)b * I_))[threadIdx.x];
    __syncthreads();

    const int k = g_idx[b];
    const int o = o0 + warp * 2;

    const float4* __restrict__ mp0 = (const float4*)(mean + ((size_t)k * O_ + o) * I_);
    const float4* __restrict__ mp1 = mp0 + I_ / 4;
    const float4* __restrict__ sp0 = g_sigma4 + ((size_t)k * O_ + o) * (I_ / 4);
    const float4* __restrict__ sp1 = sp0 + I_ / 4;
    const float4* __restrict__ ep0 = (const float4*)(eps + ((size_t)b * O_ + o) * I_);
    const float4* __restrict__ ep1 = ep0 + I_ / 4;

    float acc0 = 0.0f, acc1 = 0.0f;
#pragma unroll
    for (int j = 0; j < 4; j++) {
        const int v = j * 32 + lane;          // coalesced 512B per instruction
        float4 e0 = __ldcs(ep0 + v);          // streamed once: evict-first
        float4 e1 = __ldcs(ep1 + v);
        float4 m0 = __ldg(mp0 + v);
        float4 m1 = __ldg(mp1 + v);
        float4 s0 = __ldg(sp0 + v);
        float4 s1 = __ldg(sp1 + v);
        float4 x  = xs[v];
        acc0 = fmaf(x.x, fmaf(s0.x, e0.x, m0.x), acc0);
        acc0 = fmaf(x.y, fmaf(s0.y, e0.y, m0.y), acc0);
        acc0 = fmaf(x.z, fmaf(s0.z, e0.z, m0.z), acc0);
        acc0 = fmaf(x.w, fmaf(s0.w, e0.w, m0.w), acc0);
        acc1 = fmaf(x.x, fmaf(s1.x, e1.x, m1.x), acc1);
        acc1 = fmaf(x.y, fmaf(s1.y, e1.y, m1.y), acc1);
        acc1 = fmaf(x.z, fmaf(s1.z, e1.z, m1.z), acc1);
        acc1 = fmaf(x.w, fmaf(s1.w, e1.w, m1.w), acc1);
    }

#pragma unroll
    for (int off = 16; off; off >>= 1) {
        acc0 += __shfl_xor_sync(0xFFFFFFFFu, acc0, off);
        acc1 += __shfl_xor_sync(0xFFFFFFFFu, acc1, off);
    }

    if (lane == 0) {
        out[(size_t)b * O_ + o]     = acc0;
        out[(size_t)b * O_ + o + 1] = acc1;
    }
}

extern "C" void kernel_launch(void* const* d_in, const int* in_sizes, int n_in,
                              void* d_out, int out_size) {
    const float* X         = (const float*)d_in[0];   // [B, I]
    const float* mixw      = (const float*)d_in[1];   // [K]
    const float* mean      = (const float*)d_in[2];   // [K, O, I]
    const float* log_sigma = (const float*)d_in[3];   // [K, O, I]
    const float* u_gumbel  = (const float*)d_in[4];   // [B, K]
    const float* eps       = (const float*)d_in[5];   // [B, O, I]
    float* out = (float*)d_out;                       // [B, O]

    prep_sigma_kernel<<<(K_ * O_ * I_ / 4) / 256, 256>>>((const float4*)log_sigma);
    prep_idx_kernel<<<(B_ + 255) / 256, 256>>>(u_gumbel, mixw);
    bayes_linear_kernel<<<B_ * (O_ / 16), 256>>>(X, mean, eps, out);
}

// round 5
// speedup vs baseline: 1.0687x; 1.0216x over previous
#include <cuda_runtime.h>

#define B_ 2048
#define K_ 8
#define O_ 256
#define I_ 512
#define TINY_ 1e-10f

// Scratch (allocation-free requirement): __device__ globals.
__device__ float4 g_sigma4[K_ * O_ * I_ / 4];   // exp(log_sigma), 4 MB
__device__ int    g_idx[B_];                    // selected component per batch

#define SIGMA_BLOCKS ((K_ * O_ * I_ / 4) / 256)   // 1024
#define IDX_BLOCKS   (B_ / 256)                   // 8

// --- Kernel 1 (fused prep): sigma = exp(log_sigma)  +  per-batch argmax ---
__global__ void prep_kernel(const float4* __restrict__ log_sigma,
                            const float* __restrict__ u_gumbel,
                            const float* __restrict__ mix_weights) {
    if (blockIdx.x < SIGMA_BLOCKS) {
        int i = blockIdx.x * blockDim.x + threadIdx.x;
        float4 v = log_sigma[i];
        float4 r;
        r.x = __expf(v.x); r.y = __expf(v.y); r.z = __expf(v.z); r.w = __expf(v.w);
        g_sigma4[i] = r;
    } else {
        int b = (blockIdx.x - SIGMA_BLOCKS) * blockDim.x + threadIdx.x;
        float best = -3.402823466e+38f;
        int best_k = 0;
#pragma unroll
        for (int k = 0; k < K_; k++) {
            float u = u_gumbel[b * K_ + k];
            float g = -logf(-logf(u + TINY_) + TINY_);
            float s = mix_weights[k] + g;       // / TAU (=1)
            if (s > best) { best = s; best_k = k; }  // first-index tie-break == jnp.argmax
        }
        g_idx[b] = best_k;
    }
}

// --- Kernel 2: out[b,o] = sum_i X[b,i]*(mean[k,o,i] + sigma[k,o,i]*eps[b,o,i])
// Block = one b, 16 consecutive o; X row staged in smem.
// Each warp owns 2 o's. launch_bounds(256,4) -> 64 regs/thread so ptxas can
// front-batch ~2 unrolled iterations (12 float4 loads) of MLP.
__global__ void __launch_bounds__(256, 4)
bayes_linear_kernel(const float* __restrict__ X,
                    const float* __restrict__ mean,
                    const float* __restrict__ eps,
                    float* __restrict__ out) {
    __shared__ float4 xs[I_ / 4];     // 2 KB

    const int b  = blockIdx.x >> 4;          // 16 blocks per batch
    const int o0 = (blockIdx.x & 15) * 16;
    const int warp = threadIdx.x >> 5;
    const int lane = threadIdx.x & 31;

    if (threadIdx.x < I_ / 4)
        xs[threadIdx.x] = ((const float4*)(X + (size_t)b * I_))[threadIdx.x];
    __syncthreads();

    const int k = g_idx[b];
    const int o = o0 + warp * 2;

    const float4* __restrict__ mp0 = (const float4*)(mean + ((size_t)k * O_ + o) * I_);
    const float4* __restrict__ mp1 = mp0 + I_ / 4;
    const float4* __restrict__ sp0 = g_sigma4 + ((size_t)k * O_ + o) * (I_ / 4);
    const float4* __restrict__ sp1 = sp0 + I_ / 4;
    const float4* __restrict__ ep0 = (const float4*)(eps + ((size_t)b * O_ + o) * I_);
    const float4* __restrict__ ep1 = ep0 + I_ / 4;

    float acc0 = 0.0f, acc1 = 0.0f;
#pragma unroll
    for (int j = 0; j < 4; j++) {
        const int v = j * 32 + lane;          // coalesced 512B per instruction
        float4 e0 = __ldcs(ep0 + v);          // streamed once: evict-first
        float4 e1 = __ldcs(ep1 + v);
        float4 m0 = __ldg(mp0 + v);
        float4 m1 = __ldg(mp1 + v);
        float4 s0 = __ldg(sp0 + v);
        float4 s1 = __ldg(sp1 + v);
        float4 x  = xs[v];
        acc0 = fmaf(x.x, fmaf(s0.x, e0.x, m0.x), acc0);
        acc0 = fmaf(x.y, fmaf(s0.y, e0.y, m0.y), acc0);
        acc0 = fmaf(x.z, fmaf(s0.z, e0.z, m0.z), acc0);
        acc0 = fmaf(x.w, fmaf(s0.w, e0.w, m0.w), acc0);
        acc1 = fmaf(x.x, fmaf(s1.x, e1.x, m1.x), acc1);
        acc1 = fmaf(x.y, fmaf(s1.y, e1.y, m1.y), acc1);
        acc1 = fmaf(x.z, fmaf(s1.z, e1.z, m1.z), acc1);
        acc1 = fmaf(x.w, fmaf(s1.w, e1.w, m1.w), acc1);
    }

#pragma unroll
    for (int off = 16; off; off >>= 1) {
        acc0 += __shfl_xor_sync(0xFFFFFFFFu, acc0, off);
        acc1 += __shfl_xor_sync(0xFFFFFFFFu, acc1, off);
    }

    if (lane == 0) {
        out[(size_t)b * O_ + o]     = acc0;
        out[(size_t)b * O_ + o + 1] = acc1;
    }
}

extern "C" void kernel_launch(void* const* d_in, const int* in_sizes, int n_in,
                              void* d_out, int out_size) {
    const float* X         = (const float*)d_in[0];   // [B, I]
    const float* mixw      = (const float*)d_in[1];   // [K]
    const float* mean      = (const float*)d_in[2];   // [K, O, I]
    const float* log_sigma = (const float*)d_in[3];   // [K, O, I]
    const float* u_gumbel  = (const float*)d_in[4];   // [B, K]
    const float* eps       = (const float*)d_in[5];   // [B, O, I]
    float* out = (float*)d_out;                       // [B, O]

    prep_kernel<<<SIGMA_BLOCKS + IDX_BLOCKS, 256>>>(
        (const float4*)log_sigma, u_gumbel, mixw);
    bayes_linear_kernel<<<B_ * (O_ / 16), 256>>>(X, mean, eps, out);
}